// round 1
// baseline (speedup 1.0000x reference)
#include <cuda_runtime.h>

// ---------------------------------------------------------------------------
// Overlaps: out[i,j] = IoU(boxes0[i], boxes1[j]) if (label,batch) match else 0.
// Match probability is 1/640, so: zero-fill output (DRAM-bound ~55us), bucket
// boxes by key = label*8+batch, then compute only matching pairs (~156K IoUs).
// ---------------------------------------------------------------------------

#define NUM_CLASSES 80
#define NUM_IMAGES  8
#define NB          (NUM_CLASSES * NUM_IMAGES)   // 640 buckets
#define MAXN        16384                        // >= N0, N1 (10000)

__device__ int g_cnt0[NB], g_cnt1[NB];
__device__ int g_off0[NB + 1], g_off1[NB + 1];
__device__ int g_cur0[NB], g_cur1[NB];
__device__ int g_idx0[MAXN], g_idx1[MAXN];

// --- 1. zero-fill the output (vectorized, DRAM-write bound) ----------------
__global__ void k_zero(float4* __restrict__ out4, long n4,
                       float* __restrict__ out, long n_total) {
    long i = (long)blockIdx.x * blockDim.x + threadIdx.x;
    if (i < n4) out4[i] = make_float4(0.f, 0.f, 0.f, 0.f);
    // scalar tail (n_total not multiple of 4) handled by first few threads
    long tail_start = n4 * 4;
    long t = tail_start + i;
    if (i < 4 && t < n_total) out[t] = 0.f;
}

// --- 2. reset bucket counters ----------------------------------------------
__global__ void k_reset() {
    int t = threadIdx.x;
    if (t < NB) { g_cnt0[t] = 0; g_cnt1[t] = 0; }
}

// --- 3. histogram both sides by key ----------------------------------------
__global__ void k_hist(const int* __restrict__ lab0, const int* __restrict__ bat0, int n0,
                       const int* __restrict__ lab1, const int* __restrict__ bat1, int n1) {
    int i = blockIdx.x * blockDim.x + threadIdx.x;
    if (i < n0) atomicAdd(&g_cnt0[lab0[i] * NUM_IMAGES + bat0[i]], 1);
    if (i < n1) atomicAdd(&g_cnt1[lab1[i] * NUM_IMAGES + bat1[i]], 1);
}

// --- 4. exclusive scan over 640 buckets (one block, Hillis-Steele) ---------
__global__ void k_scan() {
    __shared__ int buf[2][NB];
    int t = threadIdx.x;   // blockDim.x == NB

    // scan side 0
    int c0 = g_cnt0[t];
    buf[0][t] = c0;
    __syncthreads();
    int src = 0;
    for (int d = 1; d < NB; d <<= 1) {
        int v = buf[src][t];
        if (t >= d) v += buf[src][t - d];
        buf[src ^ 1][t] = v;
        __syncthreads();
        src ^= 1;
    }
    int inc0 = buf[src][t];
    g_off0[t + 1] = inc0;
    g_cur0[t] = inc0 - c0;          // exclusive prefix
    if (t == 0) g_off0[0] = 0;
    __syncthreads();

    // scan side 1
    int c1 = g_cnt1[t];
    buf[0][t] = c1;
    __syncthreads();
    src = 0;
    for (int d = 1; d < NB; d <<= 1) {
        int v = buf[src][t];
        if (t >= d) v += buf[src][t - d];
        buf[src ^ 1][t] = v;
        __syncthreads();
        src ^= 1;
    }
    int inc1 = buf[src][t];
    g_off1[t + 1] = inc1;
    g_cur1[t] = inc1 - c1;
    if (t == 0) g_off1[0] = 0;
}

// --- 5. scatter indices into bucket-sorted order ----------------------------
__global__ void k_scatter(const int* __restrict__ lab0, const int* __restrict__ bat0, int n0,
                          const int* __restrict__ lab1, const int* __restrict__ bat1, int n1) {
    int i = blockIdx.x * blockDim.x + threadIdx.x;
    if (i < n0) {
        int k = lab0[i] * NUM_IMAGES + bat0[i];
        int p = atomicAdd(&g_cur0[k], 1);
        g_idx0[p] = i;
    }
    if (i < n1) {
        int k = lab1[i] * NUM_IMAGES + bat1[i];
        int p = atomicAdd(&g_cur1[k], 1);
        g_idx1[p] = i;
    }
}

// --- 6. sparse IoU: one block per bucket, all (i,j) pairs in the bucket ----
__global__ void k_compute(const float* __restrict__ b0,
                          const float* __restrict__ b1,
                          float* __restrict__ out, int ncols) {
    int b = blockIdx.x;
    int s0 = g_off0[b];
    int n0 = g_off0[b + 1] - s0;
    int s1 = g_off1[b];
    int n1 = g_off1[b + 1] - s1;
    int total = n0 * n1;

    for (int t = threadIdx.x; t < total; t += blockDim.x) {
        int i = g_idx0[s0 + t / n1];
        int j = g_idx1[s1 + t % n1];
        float4 A = *reinterpret_cast<const float4*>(b0 + 4 * (long)i);
        float4 B = *reinterpret_cast<const float4*>(b1 + 4 * (long)j);
        float x1 = fmaxf(A.x, B.x);
        float y1 = fmaxf(A.y, B.y);
        float x2 = fminf(A.z, B.z);
        float y2 = fminf(A.w, B.w);
        float inter = fmaxf(x2 - x1, 0.f) * fmaxf(y2 - y1, 0.f);
        float a0 = (A.z - A.x) * (A.w - A.y);
        float a1 = (B.z - B.x) * (B.w - B.y);
        float un = a0 + a1 - inter;
        float iou = (un > 0.f) ? (inter / un) : 0.f;
        out[(long)i * ncols + j] = iou;
    }
}

// ---------------------------------------------------------------------------
extern "C" void kernel_launch(void* const* d_in, const int* in_sizes, int n_in,
                              void* d_out, int out_size) {
    const float* b0   = (const float*)d_in[0];
    const int*   lab0 = (const int*)  d_in[1];
    const int*   bat0 = (const int*)  d_in[2];
    const float* b1   = (const float*)d_in[3];
    const int*   lab1 = (const int*)  d_in[4];
    const int*   bat1 = (const int*)  d_in[5];
    float* out = (float*)d_out;

    int n0 = in_sizes[0] / 4;
    int n1 = in_sizes[3] / 4;

    long n_total = (long)out_size;
    long n4 = n_total / 4;

    // 1. zero-fill output
    {
        long blocks = (n4 + 255) / 256;
        k_zero<<<(unsigned)blocks, 256>>>((float4*)out, n4, out, n_total);
    }
    // 2-5. bucket by (label, batch)
    k_reset<<<1, NB>>>();
    int nmax = n0 > n1 ? n0 : n1;
    k_hist<<<(nmax + 255) / 256, 256>>>(lab0, bat0, n0, lab1, bat1, n1);
    k_scan<<<1, NB>>>();
    k_scatter<<<(nmax + 255) / 256, 256>>>(lab0, bat0, n0, lab1, bat1, n1);
    // 6. sparse IoU over matching pairs only
    k_compute<<<NB, 128>>>(b0, b1, out, n1);
}